// round 11
// baseline (speedup 1.0000x reference)
#include <cuda_runtime.h>

// ---------------------------------------------------------------------------
// MOE_DISTRIBUTE_CASCADE_GRAPH — SINGLE LAUNCH, rank spread over first 128
// blocks (fixes R8, where rank ran on ONE block while the whole wave spun).
//
//   inv[i]   = stable counting-sort rank of expert_ids.flat[i]   (N = B*K)
//   out[b,h] = sum_k scales[b,k] * G[inv[b*K+k], h]
//   output   = (out, out) concatenated (2*B*H floats)
//
// Roles by linear bid = by*gridDim.x + bx (lowest bids launch first, so all
// rank blocks are in wave 1):
//   bid < nchunk : rank chunk 'bid' (256 ids, one match step), ticket;
//                  last rank block does chunk-prefix + expert-base scans,
//                  then releases g_flag.
//   others       : brief volatile spin on g_flag (wave-1 only; later waves
//                  see it set), then combine.
// Reset: end-of-grid ticket (distributed, tail-only) -> deterministic replays.
// ---------------------------------------------------------------------------

#define NBINS   256        // max experts supported (dataset uses 64)
#define NCHUNK  256        // max chunks (chunk = 256 ids -> N <= 65536)
#define CHSZ    256        // ids per chunk == threads per block
#define MAXN    (NCHUNK * CHSZ)

__device__ int g_inv[MAXN];              // chunk-local ranks
__device__ int g_hist[NBINS * NCHUNK];   // [expert][chunk]
__device__ int g_base[NBINS * NCHUNK];   // exclusive chunk prefix
__device__ int g_ebase[NBINS];           // exclusive expert prefix
__device__ unsigned g_ctr  = 0;          // rank-finish ticket (self-reset)
__device__ int      g_flag = 0;          // bases-ready flag (reset at end)
__device__ unsigned g_done = 0;          // grid-finish ticket (self-reset)

// --- fused single-launch kernel ----------------------------------------------
template <int K, bool GUARD>
__global__ void __launch_bounds__(256, 4)
moe_fused_kernel(const int* __restrict__ ids,
                 const float* __restrict__ scales,
                 const float* __restrict__ G,
                 float* __restrict__ out,
                 int B, int H4, int dup, int n, int nchunk) {
    __shared__ int   cnt[8 * NBINS];     // rank scratch (rank blocks only)
    __shared__ int   totals[NBINS];
    __shared__ int   rows[K];
    __shared__ float sc[K];
    __shared__ int   is_last;

    const int tid = threadIdx.x;
    const int b   = blockIdx.y;
    const int bid = blockIdx.y * gridDim.x + blockIdx.x;

    // scales are rank-independent -> load before any waiting
    if (tid < K) sc[tid] = scales[b * K + tid];

    if (bid < nchunk) {
        // ================= RANK: one 256-id chunk, one match step ==========
        const unsigned FULL = 0xffffffffu;
        const int w    = tid >> 5;
        const int lane = tid & 31;
        const int i    = bid * CHSZ + tid;

        for (int j = tid; j < 8 * NBINS; j += 256) cnt[j] = 0;
        __syncthreads();

        const bool valid = (i < n);
        const int  key   = valid ? ids[i] : (NBINS + lane);
        const unsigned mask = __match_any_sync(FULL, key);
        const int lower  = __popc(mask & ((1u << lane) - 1u));
        const int leader = __ffs(mask) - 1;
        if (valid && lane == leader)
            cnt[w * NBINS + key] = __popc(mask);
        __syncthreads();

        // per-expert exclusive scan over the 8 warp rows; totals -> g_hist
        {
            int run = 0;
            #pragma unroll
            for (int ww = 0; ww < 8; ww++) {
                const int h = cnt[ww * NBINS + tid];
                cnt[ww * NBINS + tid] = run;
                run += h;
            }
            g_hist[tid * NCHUNK + bid] = run;    // expert-major
        }
        __syncthreads();

        if (valid) g_inv[i] = lower + cnt[w * NBINS + key];

        __threadfence();                          // publish hist + local ranks
        __syncthreads();
        if (tid == 0)
            is_last = (atomicAdd(&g_ctr, 1u) == (unsigned)nchunk - 1u);
        __syncthreads();

        if (is_last) {
            // scan A: per-expert exclusive prefix over chunks
            int run = 0;
            #pragma unroll 8
            for (int c = 0; c < nchunk; c++) {
                const int h = g_hist[tid * NCHUNK + c];
                g_base[tid * NCHUNK + c] = run;
                run += h;
            }
            totals[tid] = run;
            __syncthreads();
            // scan B: inclusive Hillis-Steele over expert totals
            #pragma unroll
            for (int d = 1; d < NBINS; d <<= 1) {
                const int v = (tid >= d) ? totals[tid - d] : 0;
                __syncthreads();
                totals[tid] += v;
                __syncthreads();
            }
            g_ebase[tid] = (tid == 0) ? 0 : totals[tid - 1];
            if (tid == 0) g_ctr = 0;              // re-arm ticket for replay
            __threadfence();                      // publish bases
            __syncthreads();
            if (tid == 0) atomicExch(&g_flag, 1); // release
        } else {
            // non-last rank blocks also need the bases -> join the spin
            if (tid == 0)
                while (*(volatile int*)&g_flag == 0) __nanosleep(256);
            __syncthreads();
        }
    } else {
        // ================= WAIT (wave-1 only; later waves pass through) =====
        if (tid == 0)
            while (*(volatile int*)&g_flag == 0) __nanosleep(256);
        __syncthreads();
    }

    // ================= COMBINE (HBM streaming roofline body) ================
    if (tid < K) {
        const int i = b * K + tid;
        const int e = ids[i];
        rows[tid] = g_inv[i] + g_base[e * NCHUNK + (i >> 8)] + g_ebase[e];
    }
    __syncthreads();

    const int h0 = blockIdx.x * 512 + tid;
    const int h1 = h0 + 256;
    const float4* __restrict__ Gv = reinterpret_cast<const float4*>(G);
    float4* __restrict__ ov = reinterpret_cast<float4*>(out);

    const bool v0 = GUARD ? (h0 < H4) : true;
    const bool v1 = GUARD ? (h1 < H4) : true;
    float4 acc0 = make_float4(0.f, 0.f, 0.f, 0.f);
    float4 acc1 = make_float4(0.f, 0.f, 0.f, 0.f);
    #pragma unroll
    for (int k = 0; k < K; k++) {
        const float  s  = sc[k];
        const size_t rb = (size_t)rows[k] * H4;
        if (v0) {
            const float4 a = __ldg(&Gv[rb + h0]);
            acc0.x = fmaf(s, a.x, acc0.x);
            acc0.y = fmaf(s, a.y, acc0.y);
            acc0.z = fmaf(s, a.z, acc0.z);
            acc0.w = fmaf(s, a.w, acc0.w);
        }
        if (v1) {
            const float4 c = __ldg(&Gv[rb + h1]);
            acc1.x = fmaf(s, c.x, acc1.x);
            acc1.y = fmaf(s, c.y, acc1.y);
            acc1.z = fmaf(s, c.z, acc1.z);
            acc1.w = fmaf(s, c.w, acc1.w);
        }
    }
    const size_t ob = (size_t)b * H4;
    if (v0) ov[ob + h0] = acc0;
    if (v1) ov[ob + h1] = acc1;
    if (dup) {
        const size_t od = (size_t)B * H4 + ob;
        if (v0) ov[od + h0] = acc0;
        if (v1) ov[od + h1] = acc1;
    }

    // ================= RESET (last finished block; tail-only cost) ==========
    __syncthreads();
    if (tid == 0) {
        const unsigned total = gridDim.x * gridDim.y;
        if (atomicAdd(&g_done, 1u) == total - 1u) {
            g_done = 0;
            g_flag = 0;
            __threadfence();
        }
    }
}

// =================== generic fallback (any K/H; 3 plain kernels) =============
__global__ void __launch_bounds__(CHSZ, 4)
rank_local_kernel(const int* __restrict__ ids, int n) {
    __shared__ int cnt[8 * NBINS];
    const unsigned FULL = 0xffffffffu;
    const int blk = blockIdx.x, tid = threadIdx.x;
    const int w = tid >> 5, lane = tid & 31;
    const int i = blk * CHSZ + tid;
    for (int j = tid; j < 8 * NBINS; j += CHSZ) cnt[j] = 0;
    __syncthreads();
    const bool valid = (i < n);
    const int key = valid ? ids[i] : (NBINS + lane);
    const unsigned mask = __match_any_sync(FULL, key);
    const int lower = __popc(mask & ((1u << lane) - 1u));
    const int leader = __ffs(mask) - 1;
    if (valid && lane == leader) cnt[w * NBINS + key] = __popc(mask);
    __syncthreads();
    if (tid < NBINS) {
        int run = 0;
        #pragma unroll
        for (int ww = 0; ww < 8; ww++) {
            const int h = cnt[ww * NBINS + tid];
            cnt[ww * NBINS + tid] = run;
            run += h;
        }
        g_hist[tid * NCHUNK + blk] = run;
    }
    __syncthreads();
    if (valid) g_inv[i] = lower + cnt[w * NBINS + key];
}

__global__ void __launch_bounds__(NBINS, 1)
scan_kernel(int nchunk) {
    __shared__ int totals[NBINS];
    const int e = threadIdx.x;
    int run = 0;
    #pragma unroll 8
    for (int c = 0; c < nchunk; c++) {
        const int h = g_hist[e * NCHUNK + c];
        g_base[e * NCHUNK + c] = run;
        run += h;
    }
    totals[e] = run;
    __syncthreads();
    #pragma unroll
    for (int d = 1; d < NBINS; d <<= 1) {
        const int v = (e >= d) ? totals[e - d] : 0;
        __syncthreads();
        totals[e] += v;
        __syncthreads();
    }
    g_ebase[e] = (e == 0) ? 0 : totals[e - 1];
}

__global__ void __launch_bounds__(256, 4)
combine_kernel_gen(const int* __restrict__ ids,
                   const float* __restrict__ G,
                   const float* __restrict__ scales,
                   float* __restrict__ out,
                   int B, int K, int H4, int dup) {
    const int b = blockIdx.y;
    const int h = blockIdx.x * 256 + threadIdx.x;
    __shared__ int   rows[32];
    __shared__ float sc[32];
    if (threadIdx.x < (unsigned)K) {
        const int i = b * K + threadIdx.x;
        const int e = ids[i];
        rows[threadIdx.x] = g_inv[i] + g_base[e * NCHUNK + (i >> 8)]
                                     + g_ebase[e];
        sc[threadIdx.x]   = scales[i];
    }
    __syncthreads();
    if (h >= H4) return;
    const float4* __restrict__ Gv = reinterpret_cast<const float4*>(G);
    float4* __restrict__ ov = reinterpret_cast<float4*>(out);
    float4 acc = make_float4(0.f, 0.f, 0.f, 0.f);
    for (int k = 0; k < K; k++) {
        const float  s = sc[k];
        const float4 v = __ldg(&Gv[(size_t)rows[k] * H4 + h]);
        acc.x = fmaf(s, v.x, acc.x);
        acc.y = fmaf(s, v.y, acc.y);
        acc.z = fmaf(s, v.z, acc.z);
        acc.w = fmaf(s, v.w, acc.w);
    }
    const size_t o = (size_t)b * H4 + h;
    ov[o] = acc;
    if (dup) ov[(size_t)B * H4 + o] = acc;
}

// ---------------------------------------------------------------------------
extern "C" void kernel_launch(void* const* d_in, const int* in_sizes, int n_in,
                              void* d_out, int out_size) {
    // metadata order: x[B,H] f32, expert_ids[B,K] i32, expert_scales[B,K] f32,
    //                 golden_expand_x[B*K,H] f32, moe_expert_num i32
    const int*   ids    = (const int*)  d_in[1];
    const float* scales = (const float*)d_in[2];
    const float* G      = (const float*)d_in[3];
    float*       out    = (float*)d_out;

    const int N  = in_sizes[1];                     // B*K = 32768
    const long long GH = (long long)in_sizes[3];    // N*H
    const int H  = (int)(GH / N);                   // 4096
    const int B  = in_sizes[0] / H;                 // 4096
    const int K  = N / B;                           // 8
    const int H4 = H >> 2;
    const int dup = (out_size >= 2 * B * H) ? 1 : 0;
    const int nchunk = (N + CHSZ - 1) / CHSZ;       // 128

    if (K == 8 && N <= MAXN) {
        const int cpb = (H4 + 511) / 512;           // 512 float4 cols / block
        dim3 grid(cpb, B);                          // grid blocks >> nchunk
        if ((H4 & 511) == 0)
            moe_fused_kernel<8, false><<<grid, 256>>>(ids, scales, G, out,
                                                      B, H4, dup, N, nchunk);
        else
            moe_fused_kernel<8, true><<<grid, 256>>>(ids, scales, G, out,
                                                     B, H4, dup, N, nchunk);
    } else {
        rank_local_kernel<<<nchunk, CHSZ>>>(ids, N);
        scan_kernel<<<1, NBINS>>>(nchunk);
        const int cpb = (H4 + 255) / 256;
        dim3 grid(cpb, B);
        combine_kernel_gen<<<grid, 256>>>(ids, G, scales, out, B, K, H4, dup);
    }
}

// round 12
// speedup vs baseline: 1.1166x; 1.1166x over previous
#include <cuda_runtime.h>

// ---------------------------------------------------------------------------
// MOE_DISTRIBUTE_CASCADE_GRAPH — recombination of measured-best components:
//   * rank  = R2's single-block kernel (atomic SMEM histogram + match rank),
//             which measured the smallest non-combine gap of all rounds (28.8us)
//   * combine = R6's kernel (94.1us, 87.4% DRAM = traffic floor)
//   * plain 2-node launch: PDL measured neutral/negative (R9/R10),
//     fused single-launch measured badly (R8/R11).
// ---------------------------------------------------------------------------

#define NBINS   256        // max experts supported (dataset uses 64)
#define RWARPS  32         // warps in the rank block
#define RTHREADS (RWARPS * 32)
#define MAXN    65536      // max B*K supported (dataset uses 32768)

__device__ int g_inv[MAXN];

// --- Kernel 1: fused stable counting-sort rank (R2 verbatim) ----------------
// Warp w owns chunk [w*cpw, (w+1)*cpw):
//   A) per-warp SMEM-atomic histogram (results unused -> fully pipelined)
//   B) per-expert scan across warps + expert-base Hillis-Steele scan
//   C) stable rank assignment via __match_any_sync
__global__ void __launch_bounds__(RTHREADS, 1)
rank_fused_kernel(const int* __restrict__ ids, int n) {
    __shared__ int cnt[RWARPS * NBINS];   // hist -> base -> running counters
    __shared__ int totals[NBINS];
    __shared__ int totals2[NBINS];

    const int tid  = threadIdx.x;
    const int w    = tid >> 5;
    const int lane = tid & 31;
    const int cpw  = (n + RWARPS - 1) / RWARPS;   // elems per warp chunk
    const int beg  = w * cpw;
    const int end  = min(beg + cpw, n);

    // zero histograms
    for (int i = tid; i < RWARPS * NBINS; i += RTHREADS) cnt[i] = 0;
    __syncthreads();

    // A) per-warp histogram (atomics confined to this warp's 256-bin row)
    for (int i = beg + lane; i < end; i += 32)
        atomicAdd(&cnt[w * NBINS + ids[i]], 1);
    __syncthreads();

    // B1) per-expert exclusive scan over the 32 warp rows (SMEM-only chain)
    if (tid < NBINS) {
        int run = 0;
        #pragma unroll
        for (int ww = 0; ww < RWARPS; ww++) {
            const int h = cnt[ww * NBINS + tid];
            cnt[ww * NBINS + tid] = run;
            run += h;
        }
        totals[tid] = run;
    }
    __syncthreads();

    // B2) inclusive Hillis-Steele scan of expert totals
    #pragma unroll
    for (int d = 1; d < NBINS; d <<= 1) {
        int v = 0;
        if (tid < NBINS) v = (tid >= d) ? totals[tid - d] : 0;
        __syncthreads();
        if (tid < NBINS) totals2[tid] = totals[tid] + v;
        __syncthreads();
        if (tid < NBINS) totals[tid] = totals2[tid];
        __syncthreads();
    }
    // base[e] = exclusive prefix = totals[e-1]
    if (tid < NBINS) {
        const int base = (tid == 0) ? 0 : totals[tid - 1];
        #pragma unroll
        for (int ww = 0; ww < RWARPS; ww++)
            cnt[ww * NBINS + tid] += base;
    }
    __syncthreads();

    // C) stable rank assignment (match-based, in-loop loads)
    int* mycnt = &cnt[w * NBINS];
    for (int i = beg + lane; ; i += 32) {
        const bool valid = (i < end);
        const int key = valid ? ids[i] : (NBINS + lane);  // singleton if invalid
        const unsigned mask = __match_any_sync(0xffffffffu, key);
        const int lower  = __popc(mask & ((1u << lane) - 1u));
        const int leader = __ffs(mask) - 1;
        int r0 = 0;
        if (valid && lane == leader) {
            r0 = mycnt[key];
            mycnt[key] = r0 + __popc(mask);
        }
        r0 = __shfl_sync(0xffffffffu, r0, leader);
        if (valid) g_inv[i] = r0 + lower;
        if (__all_sync(0xffffffffu, i + 32 >= end)) break;
    }
}

// --- Kernel 2: gather-reduce combine (R6 verbatim) ---------------------------
// 256 threads, 4 blocks/SM, two float4 columns per thread; GUARD=false is the
// exact-fit path (H4 % 512 == 0).
template <int K, bool GUARD>
__global__ void __launch_bounds__(256, 4)
combine_kernel(const float* __restrict__ G,
               const float* __restrict__ scales,
               float* __restrict__ out,
               int B, int H4, int dup) {
    const int b  = blockIdx.y;
    const int h0 = blockIdx.x * 512 + threadIdx.x;
    const int h1 = h0 + 256;
    __shared__ int   rows[K];
    __shared__ float sc[K];
    if (threadIdx.x < K) {
        rows[threadIdx.x] = g_inv[b * K + threadIdx.x];
        sc[threadIdx.x]   = scales[b * K + threadIdx.x];
    }
    __syncthreads();

    const float4* __restrict__ Gv = reinterpret_cast<const float4*>(G);
    float4* __restrict__ ov = reinterpret_cast<float4*>(out);

    const bool v0 = GUARD ? (h0 < H4) : true;
    const bool v1 = GUARD ? (h1 < H4) : true;
    float4 acc0 = make_float4(0.f, 0.f, 0.f, 0.f);
    float4 acc1 = make_float4(0.f, 0.f, 0.f, 0.f);
    #pragma unroll
    for (int k = 0; k < K; k++) {
        const float  s  = sc[k];
        const size_t rb = (size_t)rows[k] * H4;
        if (v0) {
            const float4 a = __ldg(&Gv[rb + h0]);
            acc0.x = fmaf(s, a.x, acc0.x);
            acc0.y = fmaf(s, a.y, acc0.y);
            acc0.z = fmaf(s, a.z, acc0.z);
            acc0.w = fmaf(s, a.w, acc0.w);
        }
        if (v1) {
            const float4 c = __ldg(&Gv[rb + h1]);
            acc1.x = fmaf(s, c.x, acc1.x);
            acc1.y = fmaf(s, c.y, acc1.y);
            acc1.z = fmaf(s, c.z, acc1.z);
            acc1.w = fmaf(s, c.w, acc1.w);
        }
    }
    const size_t ob = (size_t)b * H4;
    if (v0) ov[ob + h0] = acc0;
    if (v1) ov[ob + h1] = acc1;
    if (dup) {
        const size_t od = (size_t)B * H4 + ob;
        if (v0) ov[od + h0] = acc0;
        if (v1) ov[od + h1] = acc1;
    }
}

// generic-K fallback
__global__ void __launch_bounds__(256, 4)
combine_kernel_gen(const float* __restrict__ G,
                   const float* __restrict__ scales,
                   float* __restrict__ out,
                   int B, int K, int H4, int dup) {
    const int b = blockIdx.y;
    const int h = blockIdx.x * 256 + threadIdx.x;
    __shared__ int   rows[32];
    __shared__ float sc[32];
    if (threadIdx.x < (unsigned)K) {
        rows[threadIdx.x] = g_inv[b * K + threadIdx.x];
        sc[threadIdx.x]   = scales[b * K + threadIdx.x];
    }
    __syncthreads();
    if (h >= H4) return;
    const float4* __restrict__ Gv = reinterpret_cast<const float4*>(G);
    float4* __restrict__ ov = reinterpret_cast<float4*>(out);
    float4 acc = make_float4(0.f, 0.f, 0.f, 0.f);
    for (int k = 0; k < K; k++) {
        const float  s = sc[k];
        const float4 v = __ldg(&Gv[(size_t)rows[k] * H4 + h]);
        acc.x = fmaf(s, v.x, acc.x);
        acc.y = fmaf(s, v.y, acc.y);
        acc.z = fmaf(s, v.z, acc.z);
        acc.w = fmaf(s, v.w, acc.w);
    }
    const size_t o = (size_t)b * H4 + h;
    ov[o] = acc;
    if (dup) ov[(size_t)B * H4 + o] = acc;
}

// ---------------------------------------------------------------------------
extern "C" void kernel_launch(void* const* d_in, const int* in_sizes, int n_in,
                              void* d_out, int out_size) {
    // metadata order: x[B,H] f32, expert_ids[B,K] i32, expert_scales[B,K] f32,
    //                 golden_expand_x[B*K,H] f32, moe_expert_num i32
    const int*   ids    = (const int*)  d_in[1];
    const float* scales = (const float*)d_in[2];
    const float* G      = (const float*)d_in[3];
    float*       out    = (float*)d_out;

    const int N  = in_sizes[1];                     // B*K = 32768
    const long long GH = (long long)in_sizes[3];    // N*H
    const int H  = (int)(GH / N);                   // 4096
    const int B  = in_sizes[0] / H;                 // 4096
    const int K  = N / B;                           // 8
    const int H4 = H >> 2;
    const int dup = (out_size >= 2 * B * H) ? 1 : 0;

    rank_fused_kernel<<<1, RTHREADS>>>(ids, N);

    if (K == 8) {
        const int cpb = (H4 + 511) / 512;           // 512 float4 cols / block
        dim3 grid(cpb, B);
        if ((H4 & 511) == 0)
            combine_kernel<8, false><<<grid, 256>>>(G, scales, out, B, H4, dup);
        else
            combine_kernel<8, true><<<grid, 256>>>(G, scales, out, B, H4, dup);
    } else {
        const int cpb = (H4 + 255) / 256;
        dim3 grid(cpb, B);
        combine_kernel_gen<<<grid, 256>>>(G, scales, out, B, K, H4, dup);
    }
}

// round 13
// speedup vs baseline: 1.2650x; 1.1329x over previous
#include <cuda_runtime.h>

// ---------------------------------------------------------------------------
// MOE_DISTRIBUTE_CASCADE_GRAPH — two PLAIN launches (no PDL):
//   K1: wide rank (one block per 256-id chunk): chunk-local stable ranks via
//       one __match_any_sync step + per-chunk hist; ticket-elected LAST block
//       runs both scans (int4 hist rows, register prefix) and re-arms ticket.
//   K2: combine (traffic-floor body) reconstructing inv inline:
//       inv[i] = local_rank[i] + chunk_base[e][i>>8] + expert_base[e].
// Rationale: rank on 1 SM costs ~28-30us (R2..R12); wide K1 models ~5us.
// R10 tried this via PDL/cudaLaunchKernelEx and regressed; PDL measured
// negative in R9/R10, so this round uses plain <<<>>> launches.
// ---------------------------------------------------------------------------

#define NBINS   256        // max experts supported (dataset uses 64)
#define NCHUNK  256        // max chunks (chunk = 256 ids -> N <= 65536)
#define CHSZ    256        // ids per chunk == threads per K1 block
#define MAXN    (NCHUNK * CHSZ)

__device__ int g_inv[MAXN];              // chunk-local ranks
__device__ int g_hist[NBINS * NCHUNK];   // [expert][chunk]  (expert-major)
__device__ int g_base[NBINS * NCHUNK];   // exclusive chunk prefix
__device__ int g_ebase[NBINS];           // exclusive expert prefix
__device__ unsigned g_ctr = 0;           // last-block ticket (self-resetting)

// --- K1: chunk-local stable ranks + hist; last block does both scans --------
__global__ void __launch_bounds__(CHSZ, 4)
rank_wide_kernel(const int* __restrict__ ids, int n, int nchunk) {
    __shared__ int cnt[8 * NBINS];
    __shared__ int totals[NBINS];
    __shared__ int is_last;
    const unsigned FULL = 0xffffffffu;
    const int blk  = blockIdx.x;
    const int tid  = threadIdx.x;
    const int w    = tid >> 5;
    const int lane = tid & 31;
    const int i    = blk * CHSZ + tid;

    for (int j = tid; j < 8 * NBINS; j += CHSZ) cnt[j] = 0;
    __syncthreads();

    // one match step per warp -> warp-local count/rank
    const bool valid = (i < n);
    const int  key   = valid ? ids[i] : (NBINS + lane);
    const unsigned mask = __match_any_sync(FULL, key);
    const int lower  = __popc(mask & ((1u << lane) - 1u));
    const int leader = __ffs(mask) - 1;
    if (valid && lane == leader)
        cnt[w * NBINS + key] = __popc(mask);
    __syncthreads();

    // per-expert exclusive scan over the 8 warp rows; totals -> g_hist
    {
        int run = 0;
        #pragma unroll
        for (int ww = 0; ww < 8; ww++) {
            const int h = cnt[ww * NBINS + tid];
            cnt[ww * NBINS + tid] = run;
            run += h;
        }
        g_hist[tid * NCHUNK + blk] = run;        // expert-major
    }
    __syncthreads();

    if (valid) g_inv[i] = lower + cnt[w * NBINS + key];

    // publish, then elect the last block
    __threadfence();
    __syncthreads();
    if (tid == 0)
        is_last = (atomicAdd(&g_ctr, 1u) == (unsigned)gridDim.x - 1u);
    __syncthreads();

    if (is_last) {
        __threadfence();                          // acquire all blocks' writes

        // scan A: per-expert exclusive prefix over chunks (int4-vectorized)
        int run = 0;
        if ((nchunk & 3) == 0) {
            const int4* hrow = reinterpret_cast<const int4*>(
                                   &g_hist[tid * NCHUNK]);
            int4* brow = reinterpret_cast<int4*>(&g_base[tid * NCHUNK]);
            #pragma unroll 8
            for (int c4 = 0; c4 < (nchunk >> 2); c4++) {
                const int4 h = hrow[c4];
                int4 bo;
                bo.x = run;
                bo.y = bo.x + h.x;
                bo.z = bo.y + h.y;
                bo.w = bo.z + h.z;
                run  = bo.w + h.w;
                brow[c4] = bo;
            }
        } else {
            #pragma unroll 8
            for (int c = 0; c < nchunk; c++) {
                const int h = g_hist[tid * NCHUNK + c];
                g_base[tid * NCHUNK + c] = run;
                run += h;
            }
        }
        totals[tid] = run;
        __syncthreads();

        // scan B: inclusive Hillis-Steele over expert totals (256 threads)
        #pragma unroll
        for (int d = 1; d < NBINS; d <<= 1) {
            const int v = (tid >= d) ? totals[tid - d] : 0;
            __syncthreads();
            totals[tid] += v;
            __syncthreads();
        }
        g_ebase[tid] = (tid == 0) ? 0 : totals[tid - 1];
        if (tid == 0) g_ctr = 0;                  // re-arm for next replay
    }
}

// --- K2: combine; reconstructs inv inline (local rank + bases) --------------
template <int K, bool GUARD>
__global__ void __launch_bounds__(256, 4)
combine_kernel(const int* __restrict__ ids,
               const float* __restrict__ G,
               const float* __restrict__ scales,
               float* __restrict__ out,
               int B, int H4, int dup) {
    const int b  = blockIdx.y;
    const int h0 = blockIdx.x * 512 + threadIdx.x;
    const int h1 = h0 + 256;
    __shared__ int   rows[K];
    __shared__ float sc[K];
    if (threadIdx.x < K) {
        const int i = b * K + threadIdx.x;
        const int e = ids[i];
        sc[threadIdx.x]   = scales[i];
        rows[threadIdx.x] = g_inv[i] + g_base[e * NCHUNK + (i >> 8)]
                                     + g_ebase[e];
    }
    __syncthreads();

    const float4* __restrict__ Gv = reinterpret_cast<const float4*>(G);
    float4* __restrict__ ov = reinterpret_cast<float4*>(out);

    const bool v0 = GUARD ? (h0 < H4) : true;
    const bool v1 = GUARD ? (h1 < H4) : true;
    float4 acc0 = make_float4(0.f, 0.f, 0.f, 0.f);
    float4 acc1 = make_float4(0.f, 0.f, 0.f, 0.f);
    #pragma unroll
    for (int k = 0; k < K; k++) {
        const float  s  = sc[k];
        const size_t rb = (size_t)rows[k] * H4;
        if (v0) {
            const float4 a = __ldg(&Gv[rb + h0]);
            acc0.x = fmaf(s, a.x, acc0.x);
            acc0.y = fmaf(s, a.y, acc0.y);
            acc0.z = fmaf(s, a.z, acc0.z);
            acc0.w = fmaf(s, a.w, acc0.w);
        }
        if (v1) {
            const float4 c = __ldg(&Gv[rb + h1]);
            acc1.x = fmaf(s, c.x, acc1.x);
            acc1.y = fmaf(s, c.y, acc1.y);
            acc1.z = fmaf(s, c.z, acc1.z);
            acc1.w = fmaf(s, c.w, acc1.w);
        }
    }
    const size_t ob = (size_t)b * H4;
    if (v0) ov[ob + h0] = acc0;
    if (v1) ov[ob + h1] = acc1;
    if (dup) {
        const size_t od = (size_t)B * H4 + ob;
        if (v0) ov[od + h0] = acc0;
        if (v1) ov[od + h1] = acc1;
    }
}

// generic-K fallback (same inline reconstruction)
__global__ void __launch_bounds__(256, 4)
combine_kernel_gen(const int* __restrict__ ids,
                   const float* __restrict__ G,
                   const float* __restrict__ scales,
                   float* __restrict__ out,
                   int B, int K, int H4, int dup) {
    const int b = blockIdx.y;
    const int h = blockIdx.x * 256 + threadIdx.x;
    __shared__ int   rows[32];
    __shared__ float sc[32];
    if (threadIdx.x < (unsigned)K) {
        const int i = b * K + threadIdx.x;
        const int e = ids[i];
        sc[threadIdx.x]   = scales[i];
        rows[threadIdx.x] = g_inv[i] + g_base[e * NCHUNK + (i >> 8)]
                                     + g_ebase[e];
    }
    __syncthreads();
    if (h >= H4) return;
    const float4* __restrict__ Gv = reinterpret_cast<const float4*>(G);
    float4* __restrict__ ov = reinterpret_cast<float4*>(out);
    float4 acc = make_float4(0.f, 0.f, 0.f, 0.f);
    for (int k = 0; k < K; k++) {
        const float  s = sc[k];
        const float4 v = __ldg(&Gv[(size_t)rows[k] * H4 + h]);
        acc.x = fmaf(s, v.x, acc.x);
        acc.y = fmaf(s, v.y, acc.y);
        acc.z = fmaf(s, v.z, acc.z);
        acc.w = fmaf(s, v.w, acc.w);
    }
    const size_t o = (size_t)b * H4 + h;
    ov[o] = acc;
    if (dup) ov[(size_t)B * H4 + o] = acc;
}

// ---------------------------------------------------------------------------
extern "C" void kernel_launch(void* const* d_in, const int* in_sizes, int n_in,
                              void* d_out, int out_size) {
    // metadata order: x[B,H] f32, expert_ids[B,K] i32, expert_scales[B,K] f32,
    //                 golden_expand_x[B*K,H] f32, moe_expert_num i32
    const int*   ids    = (const int*)  d_in[1];
    const float* scales = (const float*)d_in[2];
    const float* G      = (const float*)d_in[3];
    float*       out    = (float*)d_out;

    const int N  = in_sizes[1];                     // B*K = 32768
    const long long GH = (long long)in_sizes[3];    // N*H
    const int H  = (int)(GH / N);                   // 4096
    const int B  = in_sizes[0] / H;                 // 4096
    const int K  = N / B;                           // 8
    const int H4 = H >> 2;
    const int dup = (out_size >= 2 * B * H) ? 1 : 0;
    const int nchunk = (N + CHSZ - 1) / CHSZ;       // 128

    rank_wide_kernel<<<nchunk, CHSZ>>>(ids, N, nchunk);

    if (K == 8) {
        const int cpb = (H4 + 511) / 512;           // 512 float4 cols / block
        dim3 grid(cpb, B);
        if ((H4 & 511) == 0)
            combine_kernel<8, false><<<grid, 256>>>(ids, G, scales, out,
                                                    B, H4, dup);
        else
            combine_kernel<8, true><<<grid, 256>>>(ids, G, scales, out,
                                                   B, H4, dup);
    } else {
        const int cpb = (H4 + 255) / 256;
        dim3 grid(cpb, B);
        combine_kernel_gen<<<grid, 256>>>(ids, G, scales, out, B, K, H4, dup);
    }
}